// round 4
// baseline (speedup 1.0000x reference)
#include <cuda_runtime.h>

#define TT 512
#define BB 512
#define KK 8
#define VV 5
#define HH 30
#define NLL 4

// ping-pong sequence buffers (T, B, H) fp32
__device__ float g_bufA[(size_t)TT * BB * HH];
__device__ float g_bufB[(size_t)TT * BB * HH];
// preactivation buffer (T, B, 30, 4) : gate order (i,f,g,o) minor
__device__ float g_pre[(size_t)TT * BB * HH * 4];

// ---------- helpers ----------
__device__ __forceinline__ unsigned long long pk2(float lo, float hi) {
    unsigned long long r;
    asm("mov.b64 %0, {%1,%2};" : "=l"(r) : "f"(lo), "f"(hi));
    return r;
}
__device__ __forceinline__ void upk2(unsigned long long v, float& lo, float& hi) {
    asm("mov.b64 {%0,%1}, %2;" : "=f"(lo), "=f"(hi) : "l"(v));
}
__device__ __forceinline__ unsigned long long ffma2(unsigned long long a,
                                                    unsigned long long b,
                                                    unsigned long long c) {
    unsigned long long d;
    asm("fma.rn.f32x2 %0, %1, %2, %3;" : "=l"(d) : "l"(a), "l"(b), "l"(c));
    return d;
}
__device__ __forceinline__ float tanh_ap(float x) {
    float r;
    asm("tanh.approx.f32 %0, %1;" : "=f"(r) : "f"(x));
    return r;
}
__device__ __forceinline__ float sigm_ap(float x) {
    return fmaf(0.5f, tanh_ap(0.5f * x), 0.5f);
}

// ---------- kernel 1: embedding + relu + mean over K ----------
__global__ void embed_kernel(const int* __restrict__ x,
                             const float* __restrict__ w,
                             const float* __restrict__ emb) {
    __shared__ float se[VV * HH];
    for (int i = threadIdx.x; i < VV * HH; i += blockDim.x) se[i] = emb[i];
    __syncthreads();
    int idx = blockIdx.x * blockDim.x + threadIdx.x;  // over T*B*H (exact)
    int j = idx % HH;
    size_t tb = (size_t)(idx / HH);
    const int* xp = x + tb * KK;
    const float* wp = w + tb * KK;
    float s = 0.f;
#pragma unroll
    for (int k = 0; k < KK; k++) {
        float e = se[xp[k] * HH + j] * wp[k];
        s += fmaxf(e, 0.f);
    }
    g_bufA[idx] = s * (1.f / KK);
}

// ---------- kernel 2a: per-layer input GEMM ----------
// g_pre[t][b][j][g] = bih[g*30+j]+bhh[g*30+j] + sum_k in[t][b][k] * Wih[g*30+j][k]
// token per thread; weights transposed into smem as float4 over gates.
__global__ void __launch_bounds__(256, 1)
pregemm_kernel(const float* __restrict__ Wih, const float* __restrict__ bih,
               const float* __restrict__ bhh, int l) {
    const float* __restrict__ in = (l & 1) ? g_bufB : g_bufA;

    __shared__ __align__(16) float sW[HH * HH * 4];  // [k][j][4 gates]
    __shared__ __align__(16) float sB[HH * 4];

    for (int i = threadIdx.x; i < HH * HH; i += 256) {
        int k = i / HH, j = i % HH;
        float4 v = make_float4(Wih[j * HH + k], Wih[(HH + j) * HH + k],
                               Wih[(2 * HH + j) * HH + k], Wih[(3 * HH + j) * HH + k]);
        ((float4*)sW)[i] = v;
    }
    if (threadIdx.x < HH) {
        int j = threadIdx.x;
        ((float4*)sB)[j] = make_float4(bih[j] + bhh[j], bih[HH + j] + bhh[HH + j],
                                       bih[2 * HH + j] + bhh[2 * HH + j],
                                       bih[3 * HH + j] + bhh[3 * HH + j]);
    }
    __syncthreads();

    const size_t tok = (size_t)blockIdx.x * 256 + threadIdx.x;

    float xv[HH];
    {
        const float2* xp = (const float2*)(in + tok * HH);
#pragma unroll
        for (int m = 0; m < HH / 2; m++) {
            float2 v = xp[m];
            xv[2 * m] = v.x;
            xv[2 * m + 1] = v.y;
        }
    }

    ulonglong2 acc[HH];
    const ulonglong2* sBu = (const ulonglong2*)sB;
#pragma unroll
    for (int j = 0; j < HH; j++) acc[j] = sBu[j];

    const ulonglong2* sWu = (const ulonglong2*)sW;
#pragma unroll 2
    for (int k = 0; k < HH; k++) {
        unsigned long long xk2 = pk2(xv[k], xv[k]);
#pragma unroll
        for (int j = 0; j < HH; j++) {
            ulonglong2 w = sWu[k * HH + j];
            acc[j].x = ffma2(w.x, xk2, acc[j].x);
            acc[j].y = ffma2(w.y, xk2, acc[j].y);
        }
    }

    ulonglong2* outp = (ulonglong2*)g_pre + tok * HH;
#pragma unroll
    for (int j = 0; j < HH; j++) outp[j] = acc[j];
}

// ---------- kernel 2b: warp-synchronous recurrent part ----------
// grid = B/4 CTAs x 128 threads: one WARP per batch element (1 warp/SMSP).
// lane = hidden unit j (j<30): owns all 4 gate rows of j (h-part only).
// h exchanged via per-warp 32-float double-buffered smem tile; no __syncthreads.
__global__ void __launch_bounds__(128, 1)
recur_kernel(const float* __restrict__ Whh, int l) {
    float* __restrict__ out = (l & 1) ? g_bufA : g_bufB;

    __shared__ __align__(16) float hbuf[4][2][32];

    const int warp = threadIdx.x >> 5;
    const int lane = threadIdx.x & 31;
    const int b = blockIdx.x * 4 + warp;
    const bool act = lane < HH;
    const int j = act ? lane : 0;

    // weights: w2[g][m] = (Whh[(g*30+j)*30 + 2m], Whh[... + 2m+1]); m=15 -> 0
    unsigned long long w2[4][16];
#pragma unroll
    for (int g = 0; g < 4; g++) {
        const float* wr = Whh + (g * HH + j) * HH;
#pragma unroll
        for (int m = 0; m < 15; m++) w2[g][m] = pk2(wr[2 * m], wr[2 * m + 1]);
        w2[g][15] = 0ULL;
    }

    hbuf[warp][0][lane] = 0.f;
    hbuf[warp][1][lane] = 0.f;
    __syncwarp();

    const float4* pre = (const float4*)g_pre + (size_t)b * HH + j;  // + t*BB*HH
    const size_t pstride = (size_t)BB * HH;

    float4 pf[4];
#pragma unroll
    for (int i = 0; i < 4; i++) pf[i] = pre[i * pstride];

    float c = 0.f;

#define RSTEP(T, SL)                                                            \
    {                                                                           \
        float4 pa = pf[SL];                                                     \
        if ((T) + 4 < TT) pf[SL] = pre[((T) + 4) * pstride];                    \
        const ulonglong2* hp = (const ulonglong2*)&hbuf[warp][(T) & 1][0];      \
        unsigned long long a0 = 0ULL, a1 = 0ULL, a2 = 0ULL, a3 = 0ULL;          \
        _Pragma("unroll")                                                       \
        for (int m = 0; m < 8; m++) {                                           \
            ulonglong2 h2 = hp[m];                                              \
            a0 = ffma2(w2[0][2 * m], h2.x, a0);                                 \
            a1 = ffma2(w2[1][2 * m], h2.x, a1);                                 \
            a2 = ffma2(w2[2][2 * m], h2.x, a2);                                 \
            a3 = ffma2(w2[3][2 * m], h2.x, a3);                                 \
            a0 = ffma2(w2[0][2 * m + 1], h2.y, a0);                             \
            a1 = ffma2(w2[1][2 * m + 1], h2.y, a1);                             \
            a2 = ffma2(w2[2][2 * m + 1], h2.y, a2);                             \
            a3 = ffma2(w2[3][2 * m + 1], h2.y, a3);                             \
        }                                                                       \
        float lo, hi, gi, gf, gg, go;                                           \
        upk2(a0, lo, hi); gi = pa.x + lo + hi;                                  \
        upk2(a1, lo, hi); gf = pa.y + lo + hi;                                  \
        upk2(a2, lo, hi); gg = pa.z + lo + hi;                                  \
        upk2(a3, lo, hi); go = pa.w + lo + hi;                                  \
        float i_ = sigm_ap(gi), f_ = sigm_ap(gf), o_ = sigm_ap(go);             \
        float g_ = tanh_ap(gg);                                                 \
        c = fmaf(f_, c, i_ * g_);                                               \
        float h = o_ * tanh_ap(c);                                              \
        if (act) {                                                              \
            hbuf[warp][((T) + 1) & 1][j] = h;                                   \
            out[((size_t)(T)*BB + b) * HH + j] = h;                             \
        }                                                                       \
        __syncwarp();                                                           \
    }

#pragma unroll 1
    for (int t = 0; t < TT; t += 4) {
        RSTEP(t, 0)
        RSTEP(t + 1, 1)
        RSTEP(t + 2, 2)
        RSTEP(t + 3, 3)
    }
#undef RSTEP
}

// ---------- kernel 3: attention pooling + FC + softmax ----------
__global__ void __launch_bounds__(256)
attn_kernel(const float* __restrict__ W1, const float* __restrict__ b1,
            const float* __restrict__ W2, const float* __restrict__ b2,
            const float* __restrict__ fcW, const float* __restrict__ fcb,
            float* __restrict__ outp) {
    const float* __restrict__ enc = g_bufA;  // layer 3 (odd) writes A
    const int b = blockIdx.x, tid = threadIdx.x;

    __shared__ float4 sW1[HH * 16];  // (30, 64) as float4
    __shared__ float4 sB1[16];
    __shared__ float4 sW2[16];
    __shared__ float se[TT];
    __shared__ float sred[8];
    __shared__ float swsum[8][HH];
    __shared__ float spool[HH];
    __shared__ float sscal[2];

    for (int i = tid; i < HH * 16; i += 256) sW1[i] = ((const float4*)W1)[i];
    if (tid < 16) {
        sB1[tid] = ((const float4*)b1)[tid];
        sW2[tid] = ((const float4*)W2)[tid];
    }
    __syncthreads();

    const float b2v = b2[0];
    for (int tt = tid; tt < TT; tt += 256) {
        const float* hp = enc + ((size_t)tt * BB + b) * HH;
        float4 acc[16];
#pragma unroll
        for (int q = 0; q < 16; q++) acc[q] = sB1[q];
        for (int jj = 0; jj < HH; jj++) {
            float hj = __ldg(hp + jj);
#pragma unroll
            for (int q = 0; q < 16; q++) {
                float4 wv = sW1[jj * 16 + q];
                acc[q].x = fmaf(hj, wv.x, acc[q].x);
                acc[q].y = fmaf(hj, wv.y, acc[q].y);
                acc[q].z = fmaf(hj, wv.z, acc[q].z);
                acc[q].w = fmaf(hj, wv.w, acc[q].w);
            }
        }
        float e = b2v;
#pragma unroll
        for (int q = 0; q < 16; q++) {
            float4 w2 = sW2[q];
            e += fmaxf(acc[q].x, 0.f) * w2.x + fmaxf(acc[q].y, 0.f) * w2.y +
                 fmaxf(acc[q].z, 0.f) * w2.z + fmaxf(acc[q].w, 0.f) * w2.w;
        }
        se[tt] = e;
    }
    __syncthreads();

    // softmax over T
    float m = -1e30f;
    for (int i = tid; i < TT; i += 256) m = fmaxf(m, se[i]);
#pragma unroll
    for (int o = 16; o; o >>= 1) m = fmaxf(m, __shfl_xor_sync(0xffffffffu, m, o));
    if ((tid & 31) == 0) sred[tid >> 5] = m;
    __syncthreads();
    if (tid < 32) {
        float v = (tid < 8) ? sred[tid] : -1e30f;
#pragma unroll
        for (int o = 4; o; o >>= 1) v = fmaxf(v, __shfl_xor_sync(0xffffffffu, v, o));
        if (tid == 0) sscal[0] = v;
    }
    __syncthreads();
    const float M = sscal[0];
    float ssum = 0.f;
    for (int i = tid; i < TT; i += 256) {
        float e = __expf(se[i] - M);
        se[i] = e;
        ssum += e;
    }
#pragma unroll
    for (int o = 16; o; o >>= 1) ssum += __shfl_xor_sync(0xffffffffu, ssum, o);
    if ((tid & 31) == 0) sred[tid >> 5] = ssum;
    __syncthreads();
    if (tid < 32) {
        float v = (tid < 8) ? sred[tid] : 0.f;
#pragma unroll
        for (int o = 4; o; o >>= 1) v += __shfl_xor_sync(0xffffffffu, v, o);
        if (tid == 0) sscal[1] = __fdividef(1.f, v);
    }
    __syncthreads();
    const float inv = sscal[1];

    // weighted sum over time
    float pa[HH];
#pragma unroll
    for (int jj = 0; jj < HH; jj++) pa[jj] = 0.f;
    for (int tt = tid; tt < TT; tt += 256) {
        float wgt = se[tt] * inv;
        const float* hp = enc + ((size_t)tt * BB + b) * HH;
#pragma unroll
        for (int jj = 0; jj < HH; jj++) pa[jj] = fmaf(wgt, __ldg(hp + jj), pa[jj]);
    }
#pragma unroll
    for (int jj = 0; jj < HH; jj++) {
#pragma unroll
        for (int o = 16; o; o >>= 1) pa[jj] += __shfl_xor_sync(0xffffffffu, pa[jj], o);
    }
    if ((tid & 31) == 0) {
        int w = tid >> 5;
#pragma unroll
        for (int jj = 0; jj < HH; jj++) swsum[w][jj] = pa[jj];
    }
    __syncthreads();
    if (tid < HH) {
        float s = 0.f;
#pragma unroll
        for (int w = 0; w < 8; w++) s += swsum[w][tid];
        spool[tid] = s;
    }
    __syncthreads();
    if (tid == 0) {
        float l0 = fcb[0], l1 = fcb[1], l2 = fcb[2];
#pragma unroll
        for (int jj = 0; jj < HH; jj++) {
            float p = spool[jj];
            l0 = fmaf(p, fcW[jj * 3 + 0], l0);
            l1 = fmaf(p, fcW[jj * 3 + 1], l1);
            l2 = fmaf(p, fcW[jj * 3 + 2], l2);
        }
        float mx = fmaxf(l0, fmaxf(l1, l2));
        float e0 = __expf(l0 - mx), e1 = __expf(l1 - mx), e2 = __expf(l2 - mx);
        float is = __fdividef(1.f, e0 + e1 + e2);
        outp[b * 3 + 0] = e0 * is;
        outp[b * 3 + 1] = e1 * is;
        outp[b * 3 + 2] = e2 * is;
    }
}

// ---------- launch ----------
extern "C" void kernel_launch(void* const* d_in, const int* in_sizes, int n_in,
                              void* d_out, int out_size) {
    const int*   x   = (const int*)  d_in[0];
    const float* wx  = (const float*)d_in[1];
    const float* emb = (const float*)d_in[2];
    const float* Wih = (const float*)d_in[3];
    const float* Whh = (const float*)d_in[4];
    const float* bih = (const float*)d_in[5];
    const float* bhh = (const float*)d_in[6];
    const float* aW1 = (const float*)d_in[7];
    const float* ab1 = (const float*)d_in[8];
    const float* aW2 = (const float*)d_in[9];
    const float* ab2 = (const float*)d_in[10];
    const float* fcW = (const float*)d_in[11];
    const float* fcb = (const float*)d_in[12];
    float* outp = (float*)d_out;

    embed_kernel<<<(TT * BB * HH) / 256, 256>>>(x, wx, emb);
    for (int l = 0; l < NLL; l++) {
        pregemm_kernel<<<(TT * BB) / 256, 256>>>(Wih + l * 4 * HH * HH,
                                                 bih + l * 4 * HH, bhh + l * 4 * HH, l);
        recur_kernel<<<BB / 4, 128>>>(Whh + l * 4 * HH * HH, l);
    }
    attn_kernel<<<BB, 256>>>(aW1, ab1, aW2, ab2, fcW, fcb, outp);
}

// round 5
// speedup vs baseline: 1.4858x; 1.4858x over previous
#include <cuda_runtime.h>

#define TT 512
#define BB 512
#define KK 8
#define VV 5
#define HH 30
#define NLL 4

// ping-pong sequence buffers (T, B, H) fp32
__device__ float g_bufA[(size_t)TT * BB * HH];
__device__ float g_bufB[(size_t)TT * BB * HH];

// ---------- helpers ----------
__device__ __forceinline__ unsigned long long pk2(float lo, float hi) {
    unsigned long long r;
    asm("mov.b64 %0, {%1,%2};" : "=l"(r) : "f"(lo), "f"(hi));
    return r;
}
__device__ __forceinline__ void upk2(unsigned long long v, float& lo, float& hi) {
    asm("mov.b64 {%0,%1}, %2;" : "=f"(lo), "=f"(hi) : "l"(v));
}
__device__ __forceinline__ unsigned long long ffma2(unsigned long long a,
                                                    unsigned long long b,
                                                    unsigned long long c) {
    unsigned long long d;
    asm("fma.rn.f32x2 %0, %1, %2, %3;" : "=l"(d) : "l"(a), "l"(b), "l"(c));
    return d;
}
__device__ __forceinline__ float tanh_ap(float x) {
    float r;
    asm("tanh.approx.f32 %0, %1;" : "=f"(r) : "f"(x));
    return r;
}
__device__ __forceinline__ float sigm_ap(float x) {
    return fmaf(0.5f, tanh_ap(0.5f * x), 0.5f);
}

// ---------- kernel 1: embedding + relu + mean over K ----------
__global__ void embed_kernel(const int* __restrict__ x,
                             const float* __restrict__ w,
                             const float* __restrict__ emb) {
    __shared__ float se[VV * HH];
    for (int i = threadIdx.x; i < VV * HH; i += blockDim.x) se[i] = emb[i];
    __syncthreads();
    int idx = blockIdx.x * blockDim.x + threadIdx.x;  // over T*B*H (exact)
    int j = idx % HH;
    size_t tb = (size_t)(idx / HH);
    const int* xp = x + tb * KK;
    const float* wp = w + tb * KK;
    float s = 0.f;
#pragma unroll
    for (int k = 0; k < KK; k++) {
        float e = se[xp[k] * HH + j] * wp[k];
        s += fmaxf(e, 0.f);
    }
    g_bufA[idx] = s * (1.f / KK);
}

// ---------- kernel 2: all 4 LSTM layers, warp-specialized A/B ----------
// grid = 128 CTAs (1 wave), 256 threads = 4 elements x {A-warp, B-warp}.
// A-warp (even): pre[t] = x_t . Wih^T + bias, 2 steps ahead, into smem ring.
// B-warp (odd) : gates = pre[t] + h_{t-1} . Whh^T, activations, c/h update.
// Lane j (<30) owns all 4 gate rows of hidden unit j -> no shuffles.
// Per-step sync: one named bar.sync(1+el, 64). No __syncthreads in hot loop.
__global__ void __launch_bounds__(256, 1)
lstm4_kernel(const float* __restrict__ Wih_all, const float* __restrict__ Whh_all,
             const float* __restrict__ bih_all, const float* __restrict__ bhh_all) {
    __shared__ __align__(16) float4 ring[4][4][32];   // [el][slot][j] : (i,f,g,o)
    __shared__ __align__(16) float htile[4][2][32];   // [el][buf][k]
    __shared__ __align__(16) float xtile[4][32];      // [el][k]

    const int tid = threadIdx.x;
    const int warp = tid >> 5;
    const int lane = tid & 31;
    const int el = warp >> 1;
    const bool isA = (warp & 1) == 0;
    const bool act = lane < HH;
    const int j = act ? lane : 0;
    const int b = blockIdx.x * 4 + el;
    const int barid = 1 + el;

#pragma unroll 1
    for (int l = 0; l < NLL; l++) {
        const float* __restrict__ in  = (l & 1) ? g_bufB : g_bufA;
        float* __restrict__ out       = (l & 1) ? g_bufA : g_bufB;

        // role weights: A -> Wih, B -> Whh; packed (w_{2m}, w_{2m+1})
        const float* Wx = (isA ? Wih_all : Whh_all) + l * 4 * HH * HH;
        unsigned long long w2[4][15];
#pragma unroll
        for (int g = 0; g < 4; g++) {
            const float* wr = Wx + (g * HH + j) * HH;
#pragma unroll
            for (int m = 0; m < 15; m++) w2[g][m] = pk2(wr[2 * m], wr[2 * m + 1]);
        }

        unsigned long long biasU[4];
        if (isA) {
#pragma unroll
            for (int g = 0; g < 4; g++) {
                int row = l * 4 * HH + g * HH + j;
                biasU[g] = pk2(bih_all[row] + bhh_all[row], 0.f);
            }
        }

// A gate macro: read xtile[el] broadcast, 60 ffma2, produce float4 pre
#define AGATE(OUT)                                                             \
        {                                                                      \
            const ulonglong2* xp = (const ulonglong2*)&xtile[el][0];           \
            const unsigned long long xe =                                      \
                ((const unsigned long long*)&xtile[el][0])[14];                \
            unsigned long long a0 = biasU[0], a1 = biasU[1];                   \
            unsigned long long a2 = biasU[2], a3 = biasU[3];                   \
            _Pragma("unroll")                                                  \
            for (int m = 0; m < 7; m++) {                                      \
                ulonglong2 v = xp[m];                                          \
                a0 = ffma2(w2[0][2 * m], v.x, a0);                             \
                a1 = ffma2(w2[1][2 * m], v.x, a1);                             \
                a2 = ffma2(w2[2][2 * m], v.x, a2);                             \
                a3 = ffma2(w2[3][2 * m], v.x, a3);                             \
                a0 = ffma2(w2[0][2 * m + 1], v.y, a0);                         \
                a1 = ffma2(w2[1][2 * m + 1], v.y, a1);                         \
                a2 = ffma2(w2[2][2 * m + 1], v.y, a2);                         \
                a3 = ffma2(w2[3][2 * m + 1], v.y, a3);                         \
            }                                                                  \
            a0 = ffma2(w2[0][14], xe, a0);                                     \
            a1 = ffma2(w2[1][14], xe, a1);                                     \
            a2 = ffma2(w2[2][14], xe, a2);                                     \
            a3 = ffma2(w2[3][14], xe, a3);                                     \
            float lo, hi;                                                      \
            upk2(a0, lo, hi); OUT.x = lo + hi;                                 \
            upk2(a1, lo, hi); OUT.y = lo + hi;                                 \
            upk2(a2, lo, hi); OUT.z = lo + hi;                                 \
            upk2(a3, lo, hi); OUT.w = lo + hi;                                 \
        }

        float xreg = 0.f;
        float c = 0.f;

        // ---- prologue ----
        if (isA) {
            if (act) xtile[el][j] = in[(size_t)b * HH + j];
            __syncwarp();
            float4 p0;
            AGATE(p0)
            if (act) ring[el][0][j] = p0;
            __syncwarp();
            if (act) xtile[el][j] = in[((size_t)BB + b) * HH + j];
            __syncwarp();
            float4 p1;
            AGATE(p1)
            if (act) ring[el][1][j] = p1;
            if (act) xreg = in[((size_t)2 * BB + b) * HH + j];
        } else {
            htile[el][0][lane] = 0.f;
            htile[el][1][lane] = 0.f;
        }
        __syncthreads();

        // ---- main loop ----
#pragma unroll 1
        for (int t = 0; t < TT; t++) {
            if (isA) {
                if (t + 2 < TT) {
                    __syncwarp();
                    if (act) xtile[el][j] = xreg;
                    __syncwarp();
                    if (act && t + 3 < TT)
                        xreg = in[((size_t)(t + 3) * BB + b) * HH + j];
                    float4 p;
                    AGATE(p)
                    if (act) ring[el][(t + 2) & 3][j] = p;
                }
            } else {
                float4 pa = ring[el][t & 3][j];
                const ulonglong2* hp = (const ulonglong2*)&htile[el][t & 1][0];
                const unsigned long long he =
                    ((const unsigned long long*)&htile[el][t & 1][0])[14];
                unsigned long long a0 = 0ULL, a1 = 0ULL, a2 = 0ULL, a3 = 0ULL;
#pragma unroll
                for (int m = 0; m < 7; m++) {
                    ulonglong2 v = hp[m];
                    a0 = ffma2(w2[0][2 * m], v.x, a0);
                    a1 = ffma2(w2[1][2 * m], v.x, a1);
                    a2 = ffma2(w2[2][2 * m], v.x, a2);
                    a3 = ffma2(w2[3][2 * m], v.x, a3);
                    a0 = ffma2(w2[0][2 * m + 1], v.y, a0);
                    a1 = ffma2(w2[1][2 * m + 1], v.y, a1);
                    a2 = ffma2(w2[2][2 * m + 1], v.y, a2);
                    a3 = ffma2(w2[3][2 * m + 1], v.y, a3);
                }
                a0 = ffma2(w2[0][14], he, a0);
                a1 = ffma2(w2[1][14], he, a1);
                a2 = ffma2(w2[2][14], he, a2);
                a3 = ffma2(w2[3][14], he, a3);

                float lo, hi;
                upk2(a0, lo, hi); float gi = pa.x + lo + hi;
                upk2(a1, lo, hi); float gf = pa.y + lo + hi;
                upk2(a2, lo, hi); float gg = pa.z + lo + hi;
                upk2(a3, lo, hi); float go = pa.w + lo + hi;

                float i_ = sigm_ap(gi), f_ = sigm_ap(gf), o_ = sigm_ap(go);
                float g_ = tanh_ap(gg);
                c = fmaf(f_, c, i_ * g_);
                float h = o_ * tanh_ap(c);
                if (act) {
                    htile[el][(t + 1) & 1][j] = h;
                    out[((size_t)t * BB + b) * HH + j] = h;
                }
            }
            asm volatile("bar.sync %0, %1;" :: "r"(barid), "r"(64) : "memory");
        }
        __syncthreads();  // layer boundary: B's global h visible to all A warps
#undef AGATE
    }
}

// ---------- kernel 3: attention pooling + FC + softmax ----------
__global__ void __launch_bounds__(256)
attn_kernel(const float* __restrict__ W1, const float* __restrict__ b1,
            const float* __restrict__ W2, const float* __restrict__ b2,
            const float* __restrict__ fcW, const float* __restrict__ fcb,
            float* __restrict__ outp) {
    const float* __restrict__ enc = g_bufA;  // layer 3 (odd) writes A
    const int b = blockIdx.x, tid = threadIdx.x;

    __shared__ float4 sW1[HH * 16];  // (30, 64) as float4
    __shared__ float4 sB1[16];
    __shared__ float4 sW2[16];
    __shared__ float se[TT];
    __shared__ float sred[8];
    __shared__ float swsum[8][HH];
    __shared__ float spool[HH];
    __shared__ float sscal[2];

    for (int i = tid; i < HH * 16; i += 256) sW1[i] = ((const float4*)W1)[i];
    if (tid < 16) {
        sB1[tid] = ((const float4*)b1)[tid];
        sW2[tid] = ((const float4*)W2)[tid];
    }
    __syncthreads();

    const float b2v = b2[0];
    for (int tt = tid; tt < TT; tt += 256) {
        const float* hp = enc + ((size_t)tt * BB + b) * HH;
        float4 acc[16];
#pragma unroll
        for (int q = 0; q < 16; q++) acc[q] = sB1[q];
        for (int jj = 0; jj < HH; jj++) {
            float hj = __ldg(hp + jj);
#pragma unroll
            for (int q = 0; q < 16; q++) {
                float4 wv = sW1[jj * 16 + q];
                acc[q].x = fmaf(hj, wv.x, acc[q].x);
                acc[q].y = fmaf(hj, wv.y, acc[q].y);
                acc[q].z = fmaf(hj, wv.z, acc[q].z);
                acc[q].w = fmaf(hj, wv.w, acc[q].w);
            }
        }
        float e = b2v;
#pragma unroll
        for (int q = 0; q < 16; q++) {
            float4 w2 = sW2[q];
            e += fmaxf(acc[q].x, 0.f) * w2.x + fmaxf(acc[q].y, 0.f) * w2.y +
                 fmaxf(acc[q].z, 0.f) * w2.z + fmaxf(acc[q].w, 0.f) * w2.w;
        }
        se[tt] = e;
    }
    __syncthreads();

    // softmax over T
    float m = -1e30f;
    for (int i = tid; i < TT; i += 256) m = fmaxf(m, se[i]);
#pragma unroll
    for (int o = 16; o; o >>= 1) m = fmaxf(m, __shfl_xor_sync(0xffffffffu, m, o));
    if ((tid & 31) == 0) sred[tid >> 5] = m;
    __syncthreads();
    if (tid < 32) {
        float v = (tid < 8) ? sred[tid] : -1e30f;
#pragma unroll
        for (int o = 4; o; o >>= 1) v = fmaxf(v, __shfl_xor_sync(0xffffffffu, v, o));
        if (tid == 0) sscal[0] = v;
    }
    __syncthreads();
    const float M = sscal[0];
    float ssum = 0.f;
    for (int i = tid; i < TT; i += 256) {
        float e = __expf(se[i] - M);
        se[i] = e;
        ssum += e;
    }
#pragma unroll
    for (int o = 16; o; o >>= 1) ssum += __shfl_xor_sync(0xffffffffu, ssum, o);
    if ((tid & 31) == 0) sred[tid >> 5] = ssum;
    __syncthreads();
    if (tid < 32) {
        float v = (tid < 8) ? sred[tid] : 0.f;
#pragma unroll
        for (int o = 4; o; o >>= 1) v += __shfl_xor_sync(0xffffffffu, v, o);
        if (tid == 0) sscal[1] = __fdividef(1.f, v);
    }
    __syncthreads();
    const float inv = sscal[1];

    // weighted sum over time
    float pa[HH];
#pragma unroll
    for (int jj = 0; jj < HH; jj++) pa[jj] = 0.f;
    for (int tt = tid; tt < TT; tt += 256) {
        float wgt = se[tt] * inv;
        const float* hp = enc + ((size_t)tt * BB + b) * HH;
#pragma unroll
        for (int jj = 0; jj < HH; jj++) pa[jj] = fmaf(wgt, __ldg(hp + jj), pa[jj]);
    }
#pragma unroll
    for (int jj = 0; jj < HH; jj++) {
#pragma unroll
        for (int o = 16; o; o >>= 1) pa[jj] += __shfl_xor_sync(0xffffffffu, pa[jj], o);
    }
    if ((tid & 31) == 0) {
        int w = tid >> 5;
#pragma unroll
        for (int jj = 0; jj < HH; jj++) swsum[w][jj] = pa[jj];
    }
    __syncthreads();
    if (tid < HH) {
        float s = 0.f;
#pragma unroll
        for (int w = 0; w < 8; w++) s += swsum[w][tid];
        spool[tid] = s;
    }
    __syncthreads();
    if (tid == 0) {
        float l0 = fcb[0], l1 = fcb[1], l2 = fcb[2];
#pragma unroll
        for (int jj = 0; jj < HH; jj++) {
            float p = spool[jj];
            l0 = fmaf(p, fcW[jj * 3 + 0], l0);
            l1 = fmaf(p, fcW[jj * 3 + 1], l1);
            l2 = fmaf(p, fcW[jj * 3 + 2], l2);
        }
        float mx = fmaxf(l0, fmaxf(l1, l2));
        float e0 = __expf(l0 - mx), e1 = __expf(l1 - mx), e2 = __expf(l2 - mx);
        float is = __fdividef(1.f, e0 + e1 + e2);
        outp[b * 3 + 0] = e0 * is;
        outp[b * 3 + 1] = e1 * is;
        outp[b * 3 + 2] = e2 * is;
    }
}

// ---------- launch ----------
extern "C" void kernel_launch(void* const* d_in, const int* in_sizes, int n_in,
                              void* d_out, int out_size) {
    const int*   x   = (const int*)  d_in[0];
    const float* wx  = (const float*)d_in[1];
    const float* emb = (const float*)d_in[2];
    const float* Wih = (const float*)d_in[3];
    const float* Whh = (const float*)d_in[4];
    const float* bih = (const float*)d_in[5];
    const float* bhh = (const float*)d_in[6];
    const float* aW1 = (const float*)d_in[7];
    const float* ab1 = (const float*)d_in[8];
    const float* aW2 = (const float*)d_in[9];
    const float* ab2 = (const float*)d_in[10];
    const float* fcW = (const float*)d_in[11];
    const float* fcb = (const float*)d_in[12];
    float* outp = (float*)d_out;

    embed_kernel<<<(TT * BB * HH) / 256, 256>>>(x, wx, emb);
    lstm4_kernel<<<BB / 4, 256>>>(Wih, Whh, bih, bhh);
    attn_kernel<<<BB, 256>>>(aW1, ab1, aW2, ab2, fcW, fcb, outp);
}

// round 7
// speedup vs baseline: 1.7092x; 1.1503x over previous
#include <cuda_runtime.h>

#define TT 512
#define BB 512
#define KK 8
#define VV 5
#define HH 30
#define NLL 4

__device__ float g_bufA[(size_t)TT * BB * HH];  // embed output (layer-0 input)
__device__ float g_bufB[(size_t)TT * BB * HH];  // final layer output (attn input)

// ---------- helpers ----------
__device__ __forceinline__ unsigned long long pk2(float lo, float hi) {
    unsigned long long r;
    asm("mov.b64 %0, {%1,%2};" : "=l"(r) : "f"(lo), "f"(hi));
    return r;
}
__device__ __forceinline__ void upk2(unsigned long long v, float& lo, float& hi) {
    asm("mov.b64 {%0,%1}, %2;" : "=f"(lo), "=f"(hi) : "l"(v));
}
__device__ __forceinline__ unsigned long long ffma2(unsigned long long a,
                                                    unsigned long long b,
                                                    unsigned long long c) {
    unsigned long long d;
    asm("fma.rn.f32x2 %0, %1, %2, %3;" : "=l"(d) : "l"(a), "l"(b), "l"(c));
    return d;
}
__device__ __forceinline__ float tanh_ap(float x) {
    float r;
    asm("tanh.approx.f32 %0, %1;" : "=f"(r) : "f"(x));
    return r;
}
__device__ __forceinline__ float sigm_ap(float x) {
    return fmaf(0.5f, tanh_ap(0.5f * x), 0.5f);
}

// 4-gate matvec over a 30-float broadcast vector; returns raw sums per gate.
__device__ __forceinline__ float4 matvec30(const float* __restrict__ vec,
                                           const unsigned long long (&w2)[4][15]) {
    const ulonglong2* vp = (const ulonglong2*)vec;
    const unsigned long long ve = ((const unsigned long long*)vec)[14];
    unsigned long long a0 = 0ULL, a1 = 0ULL, a2 = 0ULL, a3 = 0ULL;
#pragma unroll
    for (int m = 0; m < 7; m++) {
        ulonglong2 v = vp[m];
        a0 = ffma2(w2[0][2 * m], v.x, a0);
        a1 = ffma2(w2[1][2 * m], v.x, a1);
        a2 = ffma2(w2[2][2 * m], v.x, a2);
        a3 = ffma2(w2[3][2 * m], v.x, a3);
        a0 = ffma2(w2[0][2 * m + 1], v.y, a0);
        a1 = ffma2(w2[1][2 * m + 1], v.y, a1);
        a2 = ffma2(w2[2][2 * m + 1], v.y, a2);
        a3 = ffma2(w2[3][2 * m + 1], v.y, a3);
    }
    a0 = ffma2(w2[0][14], ve, a0);
    a1 = ffma2(w2[1][14], ve, a1);
    a2 = ffma2(w2[2][14], ve, a2);
    a3 = ffma2(w2[3][14], ve, a3);
    float lo, hi;
    float4 r;
    upk2(a0, lo, hi); r.x = lo + hi;
    upk2(a1, lo, hi); r.y = lo + hi;
    upk2(a2, lo, hi); r.z = lo + hi;
    upk2(a3, lo, hi); r.w = lo + hi;
    return r;
}

// ---------- kernel 1: embedding + relu + mean over K ----------
__global__ void embed_kernel(const int* __restrict__ x,
                             const float* __restrict__ w,
                             const float* __restrict__ emb) {
    __shared__ float se[VV * HH];
    for (int i = threadIdx.x; i < VV * HH; i += blockDim.x) se[i] = emb[i];
    __syncthreads();
    int idx = blockIdx.x * blockDim.x + threadIdx.x;  // over T*B*H (exact)
    int j = idx % HH;
    size_t tb = (size_t)(idx / HH);
    const int* xp = x + tb * KK;
    const float* wp = w + tb * KK;
    float s = 0.f;
#pragma unroll
    for (int k = 0; k < KK; k++) {
        float e = se[xp[k] * HH + j] * wp[k];
        s += fmaxf(e, 0.f);
    }
    g_bufA[idx] = s * (1.f / KK);
}

// ---------- kernel 2: 4 LSTM layers, layer-pipelined wavefront ----------
// 128 CTAs x 256 threads (1 wave). CTA owns 4 batch elements.
// warp w: role A (w<4) computes pre_l[t] = x_t.Wih^T + bias (layer l = w&3);
//         role B (w>=4) computes gates/c/h for layer l = w&3.
// SMSP k hosts {A(lk), B(lk)} -> FMA/MUFU balanced per scheduler.
// Wavefront: at step s, A_l does t=s-2l, B_l does t=s-2l-1. Depth-4 smem rings;
// one __syncthreads per step; h for layers 0..2 never leaves the SM.
__global__ void __launch_bounds__(256, 1)
lstm4_pipe(const float* __restrict__ Wih_all, const float* __restrict__ Whh_all,
           const float* __restrict__ bih_all, const float* __restrict__ bhh_all) {
    __shared__ __align__(16) float4 preR[NLL][4][4][HH];  // [l][slot][el][j]
    __shared__ __align__(16) float hR[NLL][4][4][32];     // [l][slot][el][k]
    __shared__ __align__(16) float xtile[4][32];          // layer-0 input stage

    const int tid = threadIdx.x;
    const int w = tid >> 5;
    const int lane = tid & 31;
    const int l = w & 3;
    const bool isA = w < 4;
    const bool act = lane < HH;
    const int j = act ? lane : 0;
    const int b0 = blockIdx.x * 4;

    // zero h rings (slot 3 is t=-1 state; rest defensive)
    for (int i = tid; i < NLL * 4 * 4 * 32; i += 256)
        ((float*)hR)[i] = 0.f;

    // per-warp weights: A -> Wih[l], B -> Whh[l]; packed (w_{2m}, w_{2m+1})
    const float* Wx = (isA ? Wih_all : Whh_all) + l * 4 * HH * HH;
    unsigned long long w2[4][15];
#pragma unroll
    for (int g = 0; g < 4; g++) {
        const float* wr = Wx + (g * HH + j) * HH;
#pragma unroll
        for (int m = 0; m < 15; m++) w2[g][m] = pk2(wr[2 * m], wr[2 * m + 1]);
    }
    float bias[4];
    if (isA) {
#pragma unroll
        for (int g = 0; g < 4; g++) {
            int row = l * 4 * HH + g * HH + j;
            bias[g] = bih_all[row] + bhh_all[row];
        }
    }

    float xcur[4];
    if (isA && l == 0 && act) {
#pragma unroll
        for (int e = 0; e < 4; e++) xcur[e] = g_bufA[(size_t)(b0 + e) * HH + j];
    }
    float c[4] = {0.f, 0.f, 0.f, 0.f};

    __syncthreads();

#pragma unroll 1
    for (int s = 0; s < TT + 2 * NLL - 1; s++) {
        if (isA) {
            const int t = s - 2 * l;
            if (0 <= t && t < TT) {
                if (l == 0) {
                    if (act) {
#pragma unroll
                        for (int e = 0; e < 4; e++) xtile[e][j] = xcur[e];
                    }
                    __syncwarp();
                    if (act && t + 1 < TT) {
#pragma unroll
                        for (int e = 0; e < 4; e++)
                            xcur[e] = g_bufA[((size_t)(t + 1) * BB + b0 + e) * HH + j];
                    }
                }
                const int slot = t & 3;
#pragma unroll
                for (int e = 0; e < 4; e++) {
                    const float* vec = (l == 0) ? &xtile[e][0]
                                                : &hR[l - 1][slot][e][0];
                    float4 p = matvec30(vec, w2);
                    p.x += bias[0];
                    p.y += bias[1];
                    p.z += bias[2];
                    p.w += bias[3];
                    if (act) preR[l][slot][e][j] = p;
                }
            }
        } else {
            const int t = s - 2 * l - 1;
            if (0 <= t && t < TT) {
                const int slot = t & 3;
                const int pslot = (t + 3) & 3;
#pragma unroll
                for (int e = 0; e < 4; e++) {
                    float4 pa = preR[l][slot][e][j];
                    float4 hv = matvec30(&hR[l][pslot][e][0], w2);
                    float gi = pa.x + hv.x;
                    float gf = pa.y + hv.y;
                    float gg = pa.z + hv.z;
                    float go = pa.w + hv.w;
                    float i_ = sigm_ap(gi), f_ = sigm_ap(gf), o_ = sigm_ap(go);
                    float g_ = tanh_ap(gg);
                    c[e] = fmaf(f_, c[e], i_ * g_);
                    float h = o_ * tanh_ap(c[e]);
                    if (act) {
                        hR[l][slot][e][j] = h;
                        if (l == NLL - 1)
                            g_bufB[((size_t)t * BB + b0 + e) * HH + j] = h;
                    }
                }
            }
        }
        __syncthreads();
    }
}

// ---------- kernel 3: attention pooling + FC + softmax ----------
__global__ void __launch_bounds__(256)
attn_kernel(const float* __restrict__ W1, const float* __restrict__ b1,
            const float* __restrict__ W2, const float* __restrict__ b2,
            const float* __restrict__ fcW, const float* __restrict__ fcb,
            float* __restrict__ outp) {
    const float* __restrict__ enc = g_bufB;
    const int b = blockIdx.x, tid = threadIdx.x;

    __shared__ float4 sW1[HH * 16];  // (30, 64) as float4
    __shared__ float4 sB1[16];
    __shared__ float4 sW2[16];
    __shared__ float se[TT];
    __shared__ float sred[8];
    __shared__ float swsum[8][HH];
    __shared__ float spool[HH];
    __shared__ float sscal[2];

    for (int i = tid; i < HH * 16; i += 256) sW1[i] = ((const float4*)W1)[i];
    if (tid < 16) {
        sB1[tid] = ((const float4*)b1)[tid];
        sW2[tid] = ((const float4*)W2)[tid];
    }
    __syncthreads();

    const float b2v = b2[0];
    for (int tt = tid; tt < TT; tt += 256) {
        const float* hp = enc + ((size_t)tt * BB + b) * HH;
        float4 acc[16];
#pragma unroll
        for (int q = 0; q < 16; q++) acc[q] = sB1[q];
        for (int jj = 0; jj < HH; jj++) {
            float hj = __ldg(hp + jj);
#pragma unroll
            for (int q = 0; q < 16; q++) {
                float4 wv = sW1[jj * 16 + q];
                acc[q].x = fmaf(hj, wv.x, acc[q].x);
                acc[q].y = fmaf(hj, wv.y, acc[q].y);
                acc[q].z = fmaf(hj, wv.z, acc[q].z);
                acc[q].w = fmaf(hj, wv.w, acc[q].w);
            }
        }
        float e = b2v;
#pragma unroll
        for (int q = 0; q < 16; q++) {
            float4 w2 = sW2[q];
            e += fmaxf(acc[q].x, 0.f) * w2.x + fmaxf(acc[q].y, 0.f) * w2.y +
                 fmaxf(acc[q].z, 0.f) * w2.z + fmaxf(acc[q].w, 0.f) * w2.w;
        }
        se[tt] = e;
    }
    __syncthreads();

    // softmax over T
    float m = -1e30f;
    for (int i = tid; i < TT; i += 256) m = fmaxf(m, se[i]);
#pragma unroll
    for (int o = 16; o; o >>= 1) m = fmaxf(m, __shfl_xor_sync(0xffffffffu, m, o));
    if ((tid & 31) == 0) sred[tid >> 5] = m;
    __syncthreads();
    if (tid < 32) {
        float v = (tid < 8) ? sred[tid] : -1e30f;
#pragma unroll
        for (int o = 4; o; o >>= 1) v = fmaxf(v, __shfl_xor_sync(0xffffffffu, v, o));
        if (tid == 0) sscal[0] = v;
    }
    __syncthreads();
    const float M = sscal[0];
    float ssum = 0.f;
    for (int i = tid; i < TT; i += 256) {
        float e = __expf(se[i] - M);
        se[i] = e;
        ssum += e;
    }
#pragma unroll
    for (int o = 16; o; o >>= 1) ssum += __shfl_xor_sync(0xffffffffu, ssum, o);
    if ((tid & 31) == 0) sred[tid >> 5] = ssum;
    __syncthreads();
    if (tid < 32) {
        float v = (tid < 8) ? sred[tid] : 0.f;
#pragma unroll
        for (int o = 4; o; o >>= 1) v += __shfl_xor_sync(0xffffffffu, v, o);
        if (tid == 0) sscal[1] = __fdividef(1.f, v);
    }
    __syncthreads();
    const float inv = sscal[1];

    // weighted sum over time
    float pa[HH];
#pragma unroll
    for (int jj = 0; jj < HH; jj++) pa[jj] = 0.f;
    for (int tt = tid; tt < TT; tt += 256) {
        float wgt = se[tt] * inv;
        const float* hp = enc + ((size_t)tt * BB + b) * HH;
#pragma unroll
        for (int jj = 0; jj < HH; jj++) pa[jj] = fmaf(wgt, __ldg(hp + jj), pa[jj]);
    }
#pragma unroll
    for (int jj = 0; jj < HH; jj++) {
#pragma unroll
        for (int o = 16; o; o >>= 1) pa[jj] += __shfl_xor_sync(0xffffffffu, pa[jj], o);
    }
    if ((tid & 31) == 0) {
        int w = tid >> 5;
#pragma unroll
        for (int jj = 0; jj < HH; jj++) swsum[w][jj] = pa[jj];
    }
    __syncthreads();
    if (tid < HH) {
        float s = 0.f;
#pragma unroll
        for (int w = 0; w < 8; w++) s += swsum[w][tid];
        spool[tid] = s;
    }
    __syncthreads();
    if (tid == 0) {
        float l0 = fcb[0], l1 = fcb[1], l2 = fcb[2];
#pragma unroll
        for (int jj = 0; jj < HH; jj++) {
            float p = spool[jj];
            l0 = fmaf(p, fcW[jj * 3 + 0], l0);
            l1 = fmaf(p, fcW[jj * 3 + 1], l1);
            l2 = fmaf(p, fcW[jj * 3 + 2], l2);
        }
        float mx = fmaxf(l0, fmaxf(l1, l2));
        float e0 = __expf(l0 - mx), e1 = __expf(l1 - mx), e2 = __expf(l2 - mx);
        float is = __fdividef(1.f, e0 + e1 + e2);
        outp[b * 3 + 0] = e0 * is;
        outp[b * 3 + 1] = e1 * is;
        outp[b * 3 + 2] = e2 * is;
    }
}

// ---------- launch ----------
extern "C" void kernel_launch(void* const* d_in, const int* in_sizes, int n_in,
                              void* d_out, int out_size) {
    const int*   x   = (const int*)  d_in[0];
    const float* wx  = (const float*)d_in[1];
    const float* emb = (const float*)d_in[2];
    const float* Wih = (const float*)d_in[3];
    const float* Whh = (const float*)d_in[4];
    const float* bih = (const float*)d_in[5];
    const float* bhh = (const float*)d_in[6];
    const float* aW1 = (const float*)d_in[7];
    const float* ab1 = (const float*)d_in[8];
    const float* aW2 = (const float*)d_in[9];
    const float* ab2 = (const float*)d_in[10];
    const float* fcW = (const float*)d_in[11];
    const float* fcb = (const float*)d_in[12];
    float* outp = (float*)d_out;

    embed_kernel<<<(TT * BB * HH) / 256, 256>>>(x, wx, emb);
    lstm4_pipe<<<BB / 4, 256>>>(Wih, Whh, bih, bhh);
    attn_kernel<<<BB, 256>>>(aW1, ab1, aW2, ab2, fcW, fcb, outp);
}

// round 8
// speedup vs baseline: 1.7292x; 1.0117x over previous
#include <cuda_runtime.h>

#define TT 512
#define BB 512
#define KK 8
#define VV 5
#define HH 30
#define NLL 4

__device__ float g_bufA[(size_t)TT * BB * HH];  // embed output (layer-0 input)
__device__ float g_bufB[(size_t)TT * BB * HH];  // final layer output (attn input)

// ---------- helpers ----------
__device__ __forceinline__ unsigned long long pk2(float lo, float hi) {
    unsigned long long r;
    asm("mov.b64 %0, {%1,%2};" : "=l"(r) : "f"(lo), "f"(hi));
    return r;
}
__device__ __forceinline__ void upk2(unsigned long long v, float& lo, float& hi) {
    asm("mov.b64 {%0,%1}, %2;" : "=f"(lo), "=f"(hi) : "l"(v));
}
__device__ __forceinline__ unsigned long long ffma2(unsigned long long a,
                                                    unsigned long long b,
                                                    unsigned long long c) {
    unsigned long long d;
    asm("fma.rn.f32x2 %0, %1, %2, %3;" : "=l"(d) : "l"(a), "l"(b), "l"(c));
    return d;
}
__device__ __forceinline__ float tanh_ap(float x) {
    float r;
    asm("tanh.approx.f32 %0, %1;" : "=f"(r) : "f"(x));
    return r;
}
__device__ __forceinline__ float sigm_ap(float x) {
    return fmaf(0.5f, tanh_ap(0.5f * x), 0.5f);
}

// 4-gate matvec over a 30-float broadcast vector; returns raw sums per gate.
__device__ __forceinline__ float4 matvec30(const float* __restrict__ vec,
                                           const unsigned long long (&w2)[4][15]) {
    const ulonglong2* vp = (const ulonglong2*)vec;
    const unsigned long long ve = ((const unsigned long long*)vec)[14];
    unsigned long long a0 = 0ULL, a1 = 0ULL, a2 = 0ULL, a3 = 0ULL;
#pragma unroll
    for (int m = 0; m < 7; m++) {
        ulonglong2 v = vp[m];
        a0 = ffma2(w2[0][2 * m], v.x, a0);
        a1 = ffma2(w2[1][2 * m], v.x, a1);
        a2 = ffma2(w2[2][2 * m], v.x, a2);
        a3 = ffma2(w2[3][2 * m], v.x, a3);
        a0 = ffma2(w2[0][2 * m + 1], v.y, a0);
        a1 = ffma2(w2[1][2 * m + 1], v.y, a1);
        a2 = ffma2(w2[2][2 * m + 1], v.y, a2);
        a3 = ffma2(w2[3][2 * m + 1], v.y, a3);
    }
    a0 = ffma2(w2[0][14], ve, a0);
    a1 = ffma2(w2[1][14], ve, a1);
    a2 = ffma2(w2[2][14], ve, a2);
    a3 = ffma2(w2[3][14], ve, a3);
    float lo, hi;
    float4 r;
    upk2(a0, lo, hi); r.x = lo + hi;
    upk2(a1, lo, hi); r.y = lo + hi;
    upk2(a2, lo, hi); r.z = lo + hi;
    upk2(a3, lo, hi); r.w = lo + hi;
    return r;
}

// ---------- kernel 1: embedding + relu + mean over K (2 j per thread) ----------
__global__ void embed_kernel(const int* __restrict__ x,
                             const float* __restrict__ w,
                             const float* __restrict__ emb) {
    __shared__ float se[VV * HH];
    for (int i = threadIdx.x; i < VV * HH; i += blockDim.x) se[i] = emb[i];
    __syncthreads();
    int idx = blockIdx.x * blockDim.x + threadIdx.x;  // over T*B*15 (exact)
    int p = idx % (HH / 2);
    size_t tb = (size_t)(idx / (HH / 2));
    const int* xp = x + tb * KK;
    const float* wp = w + tb * KK;
    float s0 = 0.f, s1 = 0.f;
#pragma unroll
    for (int k = 0; k < KK; k++) {
        int v = xp[k];
        float wk = wp[k];
        s0 += fmaxf(se[v * HH + 2 * p] * wk, 0.f);
        s1 += fmaxf(se[v * HH + 2 * p + 1] * wk, 0.f);
    }
    float2* outp = (float2*)(g_bufA + tb * HH + 2 * p);
    *outp = make_float2(s0 * (1.f / KK), s1 * (1.f / KK));
}

// ---------- kernel 2: 4 LSTM layers, layer-pipelined wavefront ----------
// 128 CTAs x 384 threads (1 wave). CTA owns 4 batch elements.
// warps 0-3:  A_l (l=w): pre_l[t] = x_t.Wih^T + bias for ALL 4 elements.
// warps 4-11: B_l (l=(w-4)&3, epair=(w-4)>>2): gates/c/h for 2 elements.
// SMSP l hosts {A_l, B_l(01), B_l(23)} -> 3 streams, FMA floor unchanged,
// B warps at high wid get arbiter priority (recurrent critical path).
__global__ void __launch_bounds__(384, 1)
lstm4_pipe(const float* __restrict__ Wih_all, const float* __restrict__ Whh_all,
           const float* __restrict__ bih_all, const float* __restrict__ bhh_all) {
    __shared__ __align__(16) float4 preR[NLL][4][4][HH];  // [l][slot][el][j]
    __shared__ __align__(16) float hR[NLL][4][4][32];     // [l][slot][el][k]
    __shared__ __align__(16) float xtile[4][32];          // layer-0 input stage

    const int tid = threadIdx.x;
    const int w = tid >> 5;
    const int lane = tid & 31;
    const bool isA = w < 4;
    const int l = isA ? w : ((w - 4) & 3);
    const int epair = isA ? 0 : ((w - 4) >> 2);
    const bool act = lane < HH;
    const int j = act ? lane : 0;
    const int b0 = blockIdx.x * 4;

    // zero h rings
    for (int i = tid; i < NLL * 4 * 4 * 32; i += 384)
        ((float*)hR)[i] = 0.f;

    // per-warp weights: A -> Wih[l], B -> Whh[l]; packed (w_{2m}, w_{2m+1})
    const float* Wx = (isA ? Wih_all : Whh_all) + l * 4 * HH * HH;
    unsigned long long w2[4][15];
#pragma unroll
    for (int g = 0; g < 4; g++) {
        const float* wr = Wx + (g * HH + j) * HH;
#pragma unroll
        for (int m = 0; m < 15; m++) w2[g][m] = pk2(wr[2 * m], wr[2 * m + 1]);
    }
    float bias[4];
    if (isA) {
#pragma unroll
        for (int g = 0; g < 4; g++) {
            int row = l * 4 * HH + g * HH + j;
            bias[g] = bih_all[row] + bhh_all[row];
        }
    }

    float xcur[4];
    if (isA && l == 0 && act) {
#pragma unroll
        for (int e = 0; e < 4; e++) xcur[e] = g_bufA[(size_t)(b0 + e) * HH + j];
    }
    float c[2] = {0.f, 0.f};

    __syncthreads();

#pragma unroll 1
    for (int s = 0; s < TT + 2 * NLL - 1; s++) {
        if (isA) {
            const int t = s - 2 * l;
            if (0 <= t && t < TT) {
                if (l == 0) {
                    if (act) {
#pragma unroll
                        for (int e = 0; e < 4; e++) xtile[e][j] = xcur[e];
                    }
                    __syncwarp();
                    if (act && t + 1 < TT) {
#pragma unroll
                        for (int e = 0; e < 4; e++)
                            xcur[e] = g_bufA[((size_t)(t + 1) * BB + b0 + e) * HH + j];
                    }
                }
                const int slot = t & 3;
#pragma unroll
                for (int e = 0; e < 4; e++) {
                    const float* vec = (l == 0) ? &xtile[e][0]
                                                : &hR[l - 1][slot][e][0];
                    float4 p = matvec30(vec, w2);
                    p.x += bias[0];
                    p.y += bias[1];
                    p.z += bias[2];
                    p.w += bias[3];
                    if (act) preR[l][slot][e][j] = p;
                }
            }
        } else {
            const int t = s - 2 * l - 1;
            if (0 <= t && t < TT) {
                const int slot = t & 3;
                const int pslot = (t + 3) & 3;
#pragma unroll
                for (int q = 0; q < 2; q++) {
                    const int e = 2 * epair + q;
                    float4 pa = preR[l][slot][e][j];
                    float4 hv = matvec30(&hR[l][pslot][e][0], w2);
                    float gi = pa.x + hv.x;
                    float gf = pa.y + hv.y;
                    float gg = pa.z + hv.z;
                    float go = pa.w + hv.w;
                    float i_ = sigm_ap(gi), f_ = sigm_ap(gf), o_ = sigm_ap(go);
                    float g_ = tanh_ap(gg);
                    c[q] = fmaf(f_, c[q], i_ * g_);
                    float h = o_ * tanh_ap(c[q]);
                    if (act) {
                        hR[l][slot][e][j] = h;
                        if (l == NLL - 1)
                            g_bufB[((size_t)t * BB + b0 + e) * HH + j] = h;
                    }
                }
            }
        }
        __syncthreads();
    }
}

// ---------- kernel 3: attention pooling + FC + softmax ----------
__global__ void __launch_bounds__(256)
attn_kernel(const float* __restrict__ W1, const float* __restrict__ b1,
            const float* __restrict__ W2, const float* __restrict__ b2,
            const float* __restrict__ fcW, const float* __restrict__ fcb,
            float* __restrict__ outp) {
    const float* __restrict__ enc = g_bufB;
    const int b = blockIdx.x, tid = threadIdx.x;

    __shared__ float4 sW1[HH * 16];  // (30, 64) as float4
    __shared__ float4 sB1[16];
    __shared__ float4 sW2[16];
    __shared__ float se[TT];
    __shared__ float sred[8];
    __shared__ float swsum[8][HH];
    __shared__ float spool[HH];
    __shared__ float sscal[2];

    for (int i = tid; i < HH * 16; i += 256) sW1[i] = ((const float4*)W1)[i];
    if (tid < 16) {
        sB1[tid] = ((const float4*)b1)[tid];
        sW2[tid] = ((const float4*)W2)[tid];
    }
    __syncthreads();

    const float b2v = b2[0];
    for (int tt = tid; tt < TT; tt += 256) {
        const float* hp = enc + ((size_t)tt * BB + b) * HH;
        float4 acc[16];
#pragma unroll
        for (int q = 0; q < 16; q++) acc[q] = sB1[q];
        for (int jj = 0; jj < HH; jj++) {
            float hj = __ldg(hp + jj);
#pragma unroll
            for (int q = 0; q < 16; q++) {
                float4 wv = sW1[jj * 16 + q];
                acc[q].x = fmaf(hj, wv.x, acc[q].x);
                acc[q].y = fmaf(hj, wv.y, acc[q].y);
                acc[q].z = fmaf(hj, wv.z, acc[q].z);
                acc[q].w = fmaf(hj, wv.w, acc[q].w);
            }
        }
        float e = b2v;
#pragma unroll
        for (int q = 0; q < 16; q++) {
            float4 w2 = sW2[q];
            e += fmaxf(acc[q].x, 0.f) * w2.x + fmaxf(acc[q].y, 0.f) * w2.y +
                 fmaxf(acc[q].z, 0.f) * w2.z + fmaxf(acc[q].w, 0.f) * w2.w;
        }
        se[tt] = e;
    }
    __syncthreads();

    // softmax over T
    float m = -1e30f;
    for (int i = tid; i < TT; i += 256) m = fmaxf(m, se[i]);
#pragma unroll
    for (int o = 16; o; o >>= 1) m = fmaxf(m, __shfl_xor_sync(0xffffffffu, m, o));
    if ((tid & 31) == 0) sred[tid >> 5] = m;
    __syncthreads();
    if (tid < 32) {
        float v = (tid < 8) ? sred[tid] : -1e30f;
#pragma unroll
        for (int o = 4; o; o >>= 1) v = fmaxf(v, __shfl_xor_sync(0xffffffffu, v, o));
        if (tid == 0) sscal[0] = v;
    }
    __syncthreads();
    const float M = sscal[0];
    float ssum = 0.f;
    for (int i = tid; i < TT; i += 256) {
        float e = __expf(se[i] - M);
        se[i] = e;
        ssum += e;
    }
#pragma unroll
    for (int o = 16; o; o >>= 1) ssum += __shfl_xor_sync(0xffffffffu, ssum, o);
    if ((tid & 31) == 0) sred[tid >> 5] = ssum;
    __syncthreads();
    if (tid < 32) {
        float v = (tid < 8) ? sred[tid] : 0.f;
#pragma unroll
        for (int o = 4; o; o >>= 1) v += __shfl_xor_sync(0xffffffffu, v, o);
        if (tid == 0) sscal[1] = __fdividef(1.f, v);
    }
    __syncthreads();
    const float inv = sscal[1];

    // weighted sum over time
    float pa[HH];
#pragma unroll
    for (int jj = 0; jj < HH; jj++) pa[jj] = 0.f;
    for (int tt = tid; tt < TT; tt += 256) {
        float wgt = se[tt] * inv;
        const float* hp = enc + ((size_t)tt * BB + b) * HH;
#pragma unroll
        for (int jj = 0; jj < HH; jj++) pa[jj] = fmaf(wgt, __ldg(hp + jj), pa[jj]);
    }
#pragma unroll
    for (int jj = 0; jj < HH; jj++) {
#pragma unroll
        for (int o = 16; o; o >>= 1) pa[jj] += __shfl_xor_sync(0xffffffffu, pa[jj], o);
    }
    if ((tid & 31) == 0) {
        int w = tid >> 5;
#pragma unroll
        for (int jj = 0; jj < HH; jj++) swsum[w][jj] = pa[jj];
    }
    __syncthreads();
    if (tid < HH) {
        float s = 0.f;
#pragma unroll
        for (int w = 0; w < 8; w++) s += swsum[w][tid];
        spool[tid] = s;
    }
    __syncthreads();
    if (tid == 0) {
        float l0 = fcb[0], l1 = fcb[1], l2 = fcb[2];
#pragma unroll
        for (int jj = 0; jj < HH; jj++) {
            float p = spool[jj];
            l0 = fmaf(p, fcW[jj * 3 + 0], l0);
            l1 = fmaf(p, fcW[jj * 3 + 1], l1);
            l2 = fmaf(p, fcW[jj * 3 + 2], l2);
        }
        float mx = fmaxf(l0, fmaxf(l1, l2));
        float e0 = __expf(l0 - mx), e1 = __expf(l1 - mx), e2 = __expf(l2 - mx);
        float is = __fdividef(1.f, e0 + e1 + e2);
        outp[b * 3 + 0] = e0 * is;
        outp[b * 3 + 1] = e1 * is;
        outp[b * 3 + 2] = e2 * is;
    }
}

// ---------- launch ----------
extern "C" void kernel_launch(void* const* d_in, const int* in_sizes, int n_in,
                              void* d_out, int out_size) {
    const int*   x   = (const int*)  d_in[0];
    const float* wx  = (const float*)d_in[1];
    const float* emb = (const float*)d_in[2];
    const float* Wih = (const float*)d_in[3];
    const float* Whh = (const float*)d_in[4];
    const float* bih = (const float*)d_in[5];
    const float* bhh = (const float*)d_in[6];
    const float* aW1 = (const float*)d_in[7];
    const float* ab1 = (const float*)d_in[8];
    const float* aW2 = (const float*)d_in[9];
    const float* ab2 = (const float*)d_in[10];
    const float* fcW = (const float*)d_in[11];
    const float* fcb = (const float*)d_in[12];
    float* outp = (float*)d_out;

    embed_kernel<<<(TT * BB * (HH / 2)) / 256, 256>>>(x, wx, emb);
    lstm4_pipe<<<BB / 4, 384>>>(Wih, Whh, bih, bhh);
    attn_kernel<<<BB, 256>>>(aW1, ab1, aW2, ab2, fcW, fcb, outp);
}

// round 9
// speedup vs baseline: 1.7726x; 1.0251x over previous
#include <cuda_runtime.h>

#define TT 512
#define BB 512
#define KK 8
#define VV 5
#define HH 30
#define NLL 4

__device__ float g_bufA[(size_t)TT * BB * HH];  // embed output (layer-0 input)
__device__ float g_bufB[(size_t)TT * BB * HH];  // final layer output (attn input)

// ---------- helpers ----------
__device__ __forceinline__ unsigned long long pk2(float lo, float hi) {
    unsigned long long r;
    asm("mov.b64 %0, {%1,%2};" : "=l"(r) : "f"(lo), "f"(hi));
    return r;
}
__device__ __forceinline__ void upk2(unsigned long long v, float& lo, float& hi) {
    asm("mov.b64 {%0,%1}, %2;" : "=f"(lo), "=f"(hi) : "l"(v));
}
__device__ __forceinline__ unsigned long long ffma2(unsigned long long a,
                                                    unsigned long long b,
                                                    unsigned long long c) {
    unsigned long long d;
    asm("fma.rn.f32x2 %0, %1, %2, %3;" : "=l"(d) : "l"(a), "l"(b), "l"(c));
    return d;
}
__device__ __forceinline__ float tanh_ap(float x) {
    float r;
    asm("tanh.approx.f32 %0, %1;" : "=f"(r) : "f"(x));
    return r;
}
__device__ __forceinline__ float sigm_ap(float x) {
    return fmaf(0.5f, tanh_ap(0.5f * x), 0.5f);
}

// 4-gate matvec over a 30-float broadcast vector; returns raw sums per gate.
__device__ __forceinline__ float4 matvec30(const float* __restrict__ vec,
                                           const unsigned long long (&w2)[4][15]) {
    const ulonglong2* vp = (const ulonglong2*)vec;
    const unsigned long long ve = ((const unsigned long long*)vec)[14];
    unsigned long long a0 = 0ULL, a1 = 0ULL, a2 = 0ULL, a3 = 0ULL;
#pragma unroll
    for (int m = 0; m < 7; m++) {
        ulonglong2 v = vp[m];
        a0 = ffma2(w2[0][2 * m], v.x, a0);
        a1 = ffma2(w2[1][2 * m], v.x, a1);
        a2 = ffma2(w2[2][2 * m], v.x, a2);
        a3 = ffma2(w2[3][2 * m], v.x, a3);
        a0 = ffma2(w2[0][2 * m + 1], v.y, a0);
        a1 = ffma2(w2[1][2 * m + 1], v.y, a1);
        a2 = ffma2(w2[2][2 * m + 1], v.y, a2);
        a3 = ffma2(w2[3][2 * m + 1], v.y, a3);
    }
    a0 = ffma2(w2[0][14], ve, a0);
    a1 = ffma2(w2[1][14], ve, a1);
    a2 = ffma2(w2[2][14], ve, a2);
    a3 = ffma2(w2[3][14], ve, a3);
    float lo, hi;
    float4 r;
    upk2(a0, lo, hi); r.x = lo + hi;
    upk2(a1, lo, hi); r.y = lo + hi;
    upk2(a2, lo, hi); r.z = lo + hi;
    upk2(a3, lo, hi); r.w = lo + hi;
    return r;
}

// ---------- kernel 1: embedding + relu + mean over K (2 j per thread) ----------
__global__ void embed_kernel(const int* __restrict__ x,
                             const float* __restrict__ w,
                             const float* __restrict__ emb) {
    __shared__ float se[VV * HH];
    for (int i = threadIdx.x; i < VV * HH; i += blockDim.x) se[i] = emb[i];
    __syncthreads();
    int idx = blockIdx.x * blockDim.x + threadIdx.x;  // over T*B*15 (exact)
    int p = idx % (HH / 2);
    size_t tb = (size_t)(idx / (HH / 2));
    const int* xp = x + tb * KK;
    const float* wp = w + tb * KK;
    float s0 = 0.f, s1 = 0.f;
#pragma unroll
    for (int k = 0; k < KK; k++) {
        int v = xp[k];
        float wk = wp[k];
        s0 += fmaxf(se[v * HH + 2 * p] * wk, 0.f);
        s1 += fmaxf(se[v * HH + 2 * p + 1] * wk, 0.f);
    }
    float2* outp = (float2*)(g_bufA + tb * HH + 2 * p);
    *outp = make_float2(s0 * (1.f / KK), s1 * (1.f / KK));
}

// ---------- kernel 2: 4 LSTM layers, wavefront with 2-step supersteps ----------
// 128 CTAs x 384 threads (1 wave). CTA owns 4 batch elements.
// warps 0-3:  A_l (l=w): pre_l for t in {2(s-2l), 2(s-2l)+1} (all 4 elements).
// warps 4-11: B_l (l=(w-4)&3, epair=(w-4)>>2): gates/c/h for the previous pair,
//             2 elements per warp.
// ONE __syncthreads per superstep (2 timesteps) -> 263 barriers instead of 519;
// A's 480 ffma2 fill B's serial-chain stalls within each fence interval.
__global__ void __launch_bounds__(384, 1)
lstm4_pipe(const float* __restrict__ Wih_all, const float* __restrict__ Whh_all,
           const float* __restrict__ bih_all, const float* __restrict__ bhh_all) {
    __shared__ __align__(16) float4 preR[NLL][4][4][HH];  // [l][slot][el][j]
    __shared__ __align__(16) float hR[NLL][4][4][32];     // [l][slot][el][k]
    __shared__ __align__(16) float xtile[2][4][32];       // [r][el][k]

    const int tid = threadIdx.x;
    const int w = tid >> 5;
    const int lane = tid & 31;
    const bool isA = w < 4;
    const int l = isA ? w : ((w - 4) & 3);
    const int epair = isA ? 0 : ((w - 4) >> 2);
    const bool act = lane < HH;
    const int j = act ? lane : 0;
    const int b0 = blockIdx.x * 4;

    // zero h rings
    for (int i = tid; i < NLL * 4 * 4 * 32; i += 384)
        ((float*)hR)[i] = 0.f;

    // per-warp weights: A -> Wih[l], B -> Whh[l]; packed (w_{2m}, w_{2m+1})
    const float* Wx = (isA ? Wih_all : Whh_all) + l * 4 * HH * HH;
    unsigned long long w2[4][15];
#pragma unroll
    for (int g = 0; g < 4; g++) {
        const float* wr = Wx + (g * HH + j) * HH;
#pragma unroll
        for (int m = 0; m < 15; m++) w2[g][m] = pk2(wr[2 * m], wr[2 * m + 1]);
    }
    float bias[4];
    if (isA) {
#pragma unroll
        for (int g = 0; g < 4; g++) {
            int row = l * 4 * HH + g * HH + j;
            bias[g] = bih_all[row] + bhh_all[row];
        }
    }

    float xcur[2][4];
    if (isA && l == 0 && act) {
#pragma unroll
        for (int r = 0; r < 2; r++)
#pragma unroll
            for (int e = 0; e < 4; e++)
                xcur[r][e] = g_bufA[((size_t)r * BB + b0 + e) * HH + j];
    }
    float c[2] = {0.f, 0.f};

    __syncthreads();

    const int S = TT / 2 + 2 * NLL - 1;  // 263 supersteps
#pragma unroll 1
    for (int s = 0; s < S; s++) {
        if (isA) {
            const int t0 = 2 * s - 4 * l;
            if (0 <= t0 && t0 < TT) {
                if (l == 0) {
                    if (act) {
#pragma unroll
                        for (int r = 0; r < 2; r++)
#pragma unroll
                            for (int e = 0; e < 4; e++)
                                xtile[r][e][j] = xcur[r][e];
                    }
                    __syncwarp();
                    if (act && t0 + 2 < TT) {
#pragma unroll
                        for (int r = 0; r < 2; r++)
#pragma unroll
                            for (int e = 0; e < 4; e++)
                                xcur[r][e] =
                                    g_bufA[((size_t)(t0 + 2 + r) * BB + b0 + e) * HH + j];
                    }
                }
#pragma unroll
                for (int r = 0; r < 2; r++) {
                    const int t = t0 + r;
                    const int slot = t & 3;
#pragma unroll
                    for (int e = 0; e < 4; e++) {
                        const float* vec = (l == 0) ? &xtile[r][e][0]
                                                    : &hR[l - 1][slot][e][0];
                        float4 p = matvec30(vec, w2);
                        p.x += bias[0];
                        p.y += bias[1];
                        p.z += bias[2];
                        p.w += bias[3];
                        if (act) preR[l][slot][e][j] = p;
                    }
                }
            }
        } else {
            const int t0 = 2 * s - 4 * l - 2;
            if (0 <= t0 && t0 < TT) {
#pragma unroll
                for (int r = 0; r < 2; r++) {
                    const int t = t0 + r;
                    const int slot = t & 3;
                    const int pslot = (t + 3) & 3;
#pragma unroll
                    for (int q = 0; q < 2; q++) {
                        const int e = 2 * epair + q;
                        float4 pa = preR[l][slot][e][j];
                        float4 hv = matvec30(&hR[l][pslot][e][0], w2);
                        float gi = pa.x + hv.x;
                        float gf = pa.y + hv.y;
                        float gg = pa.z + hv.z;
                        float go = pa.w + hv.w;
                        float i_ = sigm_ap(gi), f_ = sigm_ap(gf), o_ = sigm_ap(go);
                        float g_ = tanh_ap(gg);
                        c[q] = fmaf(f_, c[q], i_ * g_);
                        float h = o_ * tanh_ap(c[q]);
                        if (act) {
                            hR[l][slot][e][j] = h;
                            if (l == NLL - 1)
                                g_bufB[((size_t)t * BB + b0 + e) * HH + j] = h;
                        }
                    }
                    __syncwarp();  // h[t] visible in smem before t+1's matvec
                }
            }
        }
        __syncthreads();
    }
}

// ---------- kernel 3: attention pooling + FC + softmax ----------
__global__ void __launch_bounds__(256)
attn_kernel(const float* __restrict__ W1, const float* __restrict__ b1,
            const float* __restrict__ W2, const float* __restrict__ b2,
            const float* __restrict__ fcW, const float* __restrict__ fcb,
            float* __restrict__ outp) {
    const float* __restrict__ enc = g_bufB;
    const int b = blockIdx.x, tid = threadIdx.x;

    __shared__ float4 sW1[HH * 16];  // (30, 64) as float4
    __shared__ float4 sB1[16];
    __shared__ float4 sW2[16];
    __shared__ float se[TT];
    __shared__ float sred[8];
    __shared__ float swsum[8][HH];
    __shared__ float spool[HH];
    __shared__ float sscal[2];

    for (int i = tid; i < HH * 16; i += 256) sW1[i] = ((const float4*)W1)[i];
    if (tid < 16) {
        sB1[tid] = ((const float4*)b1)[tid];
        sW2[tid] = ((const float4*)W2)[tid];
    }
    __syncthreads();

    const float b2v = b2[0];
    for (int tt = tid; tt < TT; tt += 256) {
        const float* hp = enc + ((size_t)tt * BB + b) * HH;
        float4 acc[16];
#pragma unroll
        for (int q = 0; q < 16; q++) acc[q] = sB1[q];
        for (int jj = 0; jj < HH; jj++) {
            float hj = __ldg(hp + jj);
#pragma unroll
            for (int q = 0; q < 16; q++) {
                float4 wv = sW1[jj * 16 + q];
                acc[q].x = fmaf(hj, wv.x, acc[q].x);
                acc[q].y = fmaf(hj, wv.y, acc[q].y);
                acc[q].z = fmaf(hj, wv.z, acc[q].z);
                acc[q].w = fmaf(hj, wv.w, acc[q].w);
            }
        }
        float e = b2v;
#pragma unroll
        for (int q = 0; q < 16; q++) {
            float4 w2 = sW2[q];
            e += fmaxf(acc[q].x, 0.f) * w2.x + fmaxf(acc[q].y, 0.f) * w2.y +
                 fmaxf(acc[q].z, 0.f) * w2.z + fmaxf(acc[q].w, 0.f) * w2.w;
        }
        se[tt] = e;
    }
    __syncthreads();

    // softmax over T
    float m = -1e30f;
    for (int i = tid; i < TT; i += 256) m = fmaxf(m, se[i]);
#pragma unroll
    for (int o = 16; o; o >>= 1) m = fmaxf(m, __shfl_xor_sync(0xffffffffu, m, o));
    if ((tid & 31) == 0) sred[tid >> 5] = m;
    __syncthreads();
    if (tid < 32) {
        float v = (tid < 8) ? sred[tid] : -1e30f;
#pragma unroll
        for (int o = 4; o; o >>= 1) v = fmaxf(v, __shfl_xor_sync(0xffffffffu, v, o));
        if (tid == 0) sscal[0] = v;
    }
    __syncthreads();
    const float M = sscal[0];
    float ssum = 0.f;
    for (int i = tid; i < TT; i += 256) {
        float e = __expf(se[i] - M);
        se[i] = e;
        ssum += e;
    }
#pragma unroll
    for (int o = 16; o; o >>= 1) ssum += __shfl_xor_sync(0xffffffffu, ssum, o);
    if ((tid & 31) == 0) sred[tid >> 5] = ssum;
    __syncthreads();
    if (tid < 32) {
        float v = (tid < 8) ? sred[tid] : 0.f;
#pragma unroll
        for (int o = 4; o; o >>= 1) v += __shfl_xor_sync(0xffffffffu, v, o);
        if (tid == 0) sscal[1] = __fdividef(1.f, v);
    }
    __syncthreads();
    const float inv = sscal[1];

    // weighted sum over time
    float pa[HH];
#pragma unroll
    for (int jj = 0; jj < HH; jj++) pa[jj] = 0.f;
    for (int tt = tid; tt < TT; tt += 256) {
        float wgt = se[tt] * inv;
        const float* hp = enc + ((size_t)tt * BB + b) * HH;
#pragma unroll
        for (int jj = 0; jj < HH; jj++) pa[jj] = fmaf(wgt, __ldg(hp + jj), pa[jj]);
    }
#pragma unroll
    for (int jj = 0; jj < HH; jj++) {
#pragma unroll
        for (int o = 16; o; o >>= 1) pa[jj] += __shfl_xor_sync(0xffffffffu, pa[jj], o);
    }
    if ((tid & 31) == 0) {
        int w = tid >> 5;
#pragma unroll
        for (int jj = 0; jj < HH; jj++) swsum[w][jj] = pa[jj];
    }
    __syncthreads();
    if (tid < HH) {
        float s = 0.f;
#pragma unroll
        for (int w = 0; w < 8; w++) s += swsum[w][tid];
        spool[tid] = s;
    }
    __syncthreads();
    if (tid == 0) {
        float l0 = fcb[0], l1 = fcb[1], l2 = fcb[2];
#pragma unroll
        for (int jj = 0; jj < HH; jj++) {
            float p = spool[jj];
            l0 = fmaf(p, fcW[jj * 3 + 0], l0);
            l1 = fmaf(p, fcW[jj * 3 + 1], l1);
            l2 = fmaf(p, fcW[jj * 3 + 2], l2);
        }
        float mx = fmaxf(l0, fmaxf(l1, l2));
        float e0 = __expf(l0 - mx), e1 = __expf(l1 - mx), e2 = __expf(l2 - mx);
        float is = __fdividef(1.f, e0 + e1 + e2);
        outp[b * 3 + 0] = e0 * is;
        outp[b * 3 + 1] = e1 * is;
        outp[b * 3 + 2] = e2 * is;
    }
}

// ---------- launch ----------
extern "C" void kernel_launch(void* const* d_in, const int* in_sizes, int n_in,
                              void* d_out, int out_size) {
    const int*   x   = (const int*)  d_in[0];
    const float* wx  = (const float*)d_in[1];
    const float* emb = (const float*)d_in[2];
    const float* Wih = (const float*)d_in[3];
    const float* Whh = (const float*)d_in[4];
    const float* bih = (const float*)d_in[5];
    const float* bhh = (const float*)d_in[6];
    const float* aW1 = (const float*)d_in[7];
    const float* ab1 = (const float*)d_in[8];
    const float* aW2 = (const float*)d_in[9];
    const float* ab2 = (const float*)d_in[10];
    const float* fcW = (const float*)d_in[11];
    const float* fcb = (const float*)d_in[12];
    float* outp = (float*)d_out;

    embed_kernel<<<(TT * BB * (HH / 2)) / 256, 256>>>(x, wx, emb);
    lstm4_pipe<<<BB / 4, 384>>>(Wih, Whh, bih, bhh);
    attn_kernel<<<BB, 256>>>(aW1, ab1, aW2, ab2, fcW, fcb, outp);
}